// round 7
// baseline (speedup 1.0000x reference)
#include <cuda_runtime.h>

// LDDMM Hamiltonian evolve, B=1, N=8192, D=3, sigma=0.1
// out[0 : 3N]   = -dH/dq = 400 * sum_j K_ij * <p_i,p_j> * (q_i - q_j)
// out[3N : 6N]  =  dH/dp = 2   * sum_j K_ij * p_j
// K_ij = exp(-100*|q_i-q_j|^2) = exp2(C*d2), C = -100*log2(e)
//
// d2 expanded via norms (coords centered at 0.5):
//   K_ij = E_i * exp2( s_j + cq_j . m2q_i ),  E_i = exp2(C*|cq_i|^2)
// 14 packed f32x2 fma-pipe ops per 2 j-points per i.
// R7: 2 i-points per thread (TI=64) — one j LDS feeds two i-chains;
// doubles ILP, halves LDS traffic. Zero-init + atomic-add epilogue.

#define NPTS 8192
#define TI 64              // threads per CTA; CTA covers 2*TI = 128 i
#define IBLK (2 * TI)      // 128 i per CTA
#define JSPLIT 16          // j-dimension partitions
#define JC (NPTS / JSPLIT) // 512 j per CTA
#define JPAIRS (JC / 2)    // 256 packed pairs
#define HALFSZ (NPTS * 3)  // floats per output half
#define OUTSZ (2 * HALFSZ) // 49152 floats

typedef unsigned long long u64;

__device__ __forceinline__ u64 pack2(float lo, float hi) {
    u64 r; asm("mov.b64 %0, {%1, %2};" : "=l"(r) : "f"(lo), "f"(hi)); return r;
}
__device__ __forceinline__ void unpack2(u64 v, float& lo, float& hi) {
    asm("mov.b64 {%0, %1}, %2;" : "=f"(lo), "=f"(hi) : "l"(v));
}
__device__ __forceinline__ u64 fma2(u64 a, u64 b, u64 c) {
    u64 r; asm("fma.rn.f32x2 %0, %1, %2, %3;" : "=l"(r) : "l"(a), "l"(b), "l"(c)); return r;
}
__device__ __forceinline__ u64 add2(u64 a, u64 b) {
    u64 r; asm("add.rn.f32x2 %0, %1, %2;" : "=l"(r) : "l"(a), "l"(b)); return r;
}
__device__ __forceinline__ u64 mul2(u64 a, u64 b) {
    u64 r; asm("mul.rn.f32x2 %0, %1, %2;" : "=l"(r) : "l"(a), "l"(b)); return r;
}
__device__ __forceinline__ u64 ex2_2(u64 x) {
    u64 r;
    asm("{\n\t"
        ".reg .f32 l, h;\n\t"
        "mov.b64 {l, h}, %1;\n\t"
        "ex2.approx.ftz.f32 l, l;\n\t"
        "ex2.approx.ftz.f32 h, h;\n\t"
        "mov.b64 %0, {l, h};\n\t"
        "}" : "=l"(r) : "l"(x));
    return r;
}
__device__ __forceinline__ float fast_ex2(float x) {
    float y; asm("ex2.approx.ftz.f32 %0, %1;" : "=f"(y) : "f"(x)); return y;
}

#define CKER (-144.26950408889634f)   // -100 * log2(e)

__global__ __launch_bounds__(128)
void lddmm_zero_kernel(float* __restrict__ out) {
    const int v = blockIdx.x * blockDim.x + threadIdx.x;
    reinterpret_cast<float4*>(out)[v] = make_float4(0.f, 0.f, 0.f, 0.f);
}

__global__ __launch_bounds__(TI, 7)   // 448 thr/SM -> ~146 regs available
void lddmm_partial_kernel(const float* __restrict__ mom,
                          const float* __restrict__ q,
                          float* __restrict__ out) {
    // Per j-pair: [cqx|cqy][cqz|sj][pjx|pjy] as 3x LDS.128, pjz LDS.64
    __shared__ __align__(16) u64 s[JPAIRS * 6];
    __shared__ __align__(16) u64 sz[JPAIRS];

    const int js = blockIdx.y;
    const int jbase = js * JC;

    for (int p = threadIdx.x; p < JPAIRS; p += TI) {
        const int j0 = jbase + 2 * p;
        const int j1 = j0 + 1;
        const float x0 = q[j0 * 3 + 0] - 0.5f, x1 = q[j1 * 3 + 0] - 0.5f;
        const float y0 = q[j0 * 3 + 1] - 0.5f, y1 = q[j1 * 3 + 1] - 0.5f;
        const float z0 = q[j0 * 3 + 2] - 0.5f, z1 = q[j1 * 3 + 2] - 0.5f;
        const float s0 = CKER * (x0 * x0 + y0 * y0 + z0 * z0);
        const float s1 = CKER * (x1 * x1 + y1 * y1 + z1 * z1);
        s[p * 6 + 0] = pack2(x0, x1);
        s[p * 6 + 1] = pack2(y0, y1);
        s[p * 6 + 2] = pack2(z0, z1);
        s[p * 6 + 3] = pack2(s0, s1);
        s[p * 6 + 4] = pack2(mom[j0 * 3 + 0], mom[j1 * 3 + 0]);
        s[p * 6 + 5] = pack2(mom[j0 * 3 + 1], mom[j1 * 3 + 1]);
        sz[p]        = pack2(mom[j0 * 3 + 2], mom[j1 * 3 + 2]);
    }
    __syncthreads();

    // Two i-points per thread, strided by TI for coalesced loads.
    const int i0 = blockIdx.x * IBLK + threadIdx.x;
    const int i1 = i0 + TI;

    const float cqx0 = q[i0 * 3 + 0] - 0.5f, cqy0 = q[i0 * 3 + 1] - 0.5f, cqz0 = q[i0 * 3 + 2] - 0.5f;
    const float cqx1 = q[i1 * 3 + 0] - 0.5f, cqy1 = q[i1 * 3 + 1] - 0.5f, cqz1 = q[i1 * 3 + 2] - 0.5f;
    const float px0 = mom[i0 * 3 + 0], py0 = mom[i0 * 3 + 1], pz0 = mom[i0 * 3 + 2];
    const float px1 = mom[i1 * 3 + 0], py1 = mom[i1 * 3 + 1], pz1 = mom[i1 * 3 + 2];

    const u64 M2X0 = pack2(-2.0f * CKER * cqx0, -2.0f * CKER * cqx0);
    const u64 M2Y0 = pack2(-2.0f * CKER * cqy0, -2.0f * CKER * cqy0);
    const u64 M2Z0 = pack2(-2.0f * CKER * cqz0, -2.0f * CKER * cqz0);
    const u64 M2X1 = pack2(-2.0f * CKER * cqx1, -2.0f * CKER * cqx1);
    const u64 M2Y1 = pack2(-2.0f * CKER * cqy1, -2.0f * CKER * cqy1);
    const u64 M2Z1 = pack2(-2.0f * CKER * cqz1, -2.0f * CKER * cqz1);
    const u64 PX0 = pack2(px0, px0), PY0 = pack2(py0, py0), PZ0 = pack2(pz0, pz0);
    const u64 PX1 = pack2(px1, px1), PY1 = pack2(py1, py1), PZ1 = pack2(pz1, pz1);

    u64 B00 = 0, B01 = 0, B02 = 0, A00 = 0, A01 = 0, A02 = 0, W0 = 0;
    u64 B10 = 0, B11 = 0, B12 = 0, A10 = 0, A11 = 0, A12 = 0, W1 = 0;

#pragma unroll 2
    for (int p = 0; p < JPAIRS; p++) {
        const ulonglong2 w0 = *reinterpret_cast<const ulonglong2*>(&s[p * 6 + 0]);
        const ulonglong2 w1 = *reinterpret_cast<const ulonglong2*>(&s[p * 6 + 2]);
        const ulonglong2 w2 = *reinterpret_cast<const ulonglong2*>(&s[p * 6 + 4]);
        const u64 mz = sz[p];
        const u64 jx = w0.x, jy = w0.y, jz = w1.x, sj = w1.y;
        const u64 mx = w2.x, my = w2.y;

        // --- i0 chain ---
        u64 t0 = fma2(jx, M2X0, sj);
        t0 = fma2(jy, M2Y0, t0);
        t0 = fma2(jz, M2Z0, t0);
        const u64 K0 = ex2_2(t0);
        const u64 pd0 = fma2(PX0, mx, fma2(PY0, my, mul2(PZ0, mz)));
        B00 = fma2(K0, mx, B00);
        B01 = fma2(K0, my, B01);
        B02 = fma2(K0, mz, B02);
        const u64 ww0 = mul2(K0, pd0);
        W0  = add2(W0, ww0);
        A00 = fma2(ww0, jx, A00);
        A01 = fma2(ww0, jy, A01);
        A02 = fma2(ww0, jz, A02);

        // --- i1 chain (independent) ---
        u64 t1 = fma2(jx, M2X1, sj);
        t1 = fma2(jy, M2Y1, t1);
        t1 = fma2(jz, M2Z1, t1);
        const u64 K1 = ex2_2(t1);
        const u64 pd1 = fma2(PX1, mx, fma2(PY1, my, mul2(PZ1, mz)));
        B10 = fma2(K1, mx, B10);
        B11 = fma2(K1, my, B11);
        B12 = fma2(K1, mz, B12);
        const u64 ww1 = mul2(K1, pd1);
        W1  = add2(W1, ww1);
        A10 = fma2(ww1, jx, A10);
        A11 = fma2(ww1, jy, A11);
        A12 = fma2(ww1, jz, A12);
    }

    // Epilogue for i0
    {
        const float Ei = fast_ex2(CKER * (cqx0 * cqx0 + cqy0 * cqy0 + cqz0 * cqz0));
        const float eq = 400.0f * Ei, ep = 2.0f * Ei;
        float l, h, Ws, A0s, A1s, A2s, B0s, B1s, B2s;
        unpack2(W0,  l, h); Ws  = l + h;
        unpack2(A00, l, h); A0s = l + h;
        unpack2(A01, l, h); A1s = l + h;
        unpack2(A02, l, h); A2s = l + h;
        unpack2(B00, l, h); B0s = l + h;
        unpack2(B01, l, h); B1s = l + h;
        unpack2(B02, l, h); B2s = l + h;
        atomicAdd(&out[i0 * 3 + 0], eq * fmaf(Ws, cqx0, -A0s));
        atomicAdd(&out[i0 * 3 + 1], eq * fmaf(Ws, cqy0, -A1s));
        atomicAdd(&out[i0 * 3 + 2], eq * fmaf(Ws, cqz0, -A2s));
        atomicAdd(&out[HALFSZ + i0 * 3 + 0], ep * B0s);
        atomicAdd(&out[HALFSZ + i0 * 3 + 1], ep * B1s);
        atomicAdd(&out[HALFSZ + i0 * 3 + 2], ep * B2s);
    }
    // Epilogue for i1
    {
        const float Ei = fast_ex2(CKER * (cqx1 * cqx1 + cqy1 * cqy1 + cqz1 * cqz1));
        const float eq = 400.0f * Ei, ep = 2.0f * Ei;
        float l, h, Ws, A0s, A1s, A2s, B0s, B1s, B2s;
        unpack2(W1,  l, h); Ws  = l + h;
        unpack2(A10, l, h); A0s = l + h;
        unpack2(A11, l, h); A1s = l + h;
        unpack2(A12, l, h); A2s = l + h;
        unpack2(B10, l, h); B0s = l + h;
        unpack2(B11, l, h); B1s = l + h;
        unpack2(B12, l, h); B2s = l + h;
        atomicAdd(&out[i1 * 3 + 0], eq * fmaf(Ws, cqx1, -A0s));
        atomicAdd(&out[i1 * 3 + 1], eq * fmaf(Ws, cqy1, -A1s));
        atomicAdd(&out[i1 * 3 + 2], eq * fmaf(Ws, cqz1, -A2s));
        atomicAdd(&out[HALFSZ + i1 * 3 + 0], ep * B0s);
        atomicAdd(&out[HALFSZ + i1 * 3 + 1], ep * B1s);
        atomicAdd(&out[HALFSZ + i1 * 3 + 2], ep * B2s);
    }
}

extern "C" void kernel_launch(void* const* d_in, const int* in_sizes, int n_in,
                              void* d_out, int out_size) {
    const float* mom = (const float*)d_in[0];            // [1,8192,3]
    const float* control_points = (const float*)d_in[1]; // [1,8192,3]
    float* out = (float*)d_out;                          // [2*8192*3]

    lddmm_zero_kernel<<<(OUTSZ / 4) / 128, 128>>>(out);

    dim3 grid(NPTS / IBLK, JSPLIT);   // 64 x 16 = 1024 CTAs, 7/SM, one wave
    lddmm_partial_kernel<<<grid, TI>>>(mom, control_points, out);
}